// round 11
// baseline (speedup 1.0000x reference)
#include <cuda_runtime.h>
#include <cstdint>

#define NUM_C   64
#define FD      128
#define FD4     32
#define BLK     256
#define NWARP   8
#define GRID    296          // 2 blocks per SM, exactly one wave
#define PER_CAP 3456         // ceil(1e6/296)=3379
#define G       4            // rows per TMA group
#define R       4            // ring depth (groups) per warp
#define ROWB    512          // bytes per feature row
#define N_PAIRS 2016

// dynamic smem layout
#define RING_OFF  0
#define RING_SZ   (NWARP * R * G * ROWB)          // 64 KB
#define SACC_OFF  RING_SZ                          // 32 KB
#define SCOMB_OFF (SACC_OFF + NUM_C * FD * 4)
#define SMEM_DYN  (SCOMB_OFF + PER_CAP * 4)        // ~110.8 KB

__device__ float        g_sums[NUM_C * FD];
__device__ int          g_counts[NUM_C];
__device__ float        g_sumsq;
__device__ unsigned int g_ticket;

__device__ __forceinline__ void mbar_init(uint32_t mbar, uint32_t cnt) {
    asm volatile("mbarrier.init.shared.b64 [%0], %1;" :: "r"(mbar), "r"(cnt) : "memory");
}
__device__ __forceinline__ void mbar_expect_tx(uint32_t mbar, uint32_t bytes) {
    asm volatile("mbarrier.arrive.expect_tx.shared.b64 _, [%0], %1;"
                 :: "r"(mbar), "r"(bytes) : "memory");
}
__device__ __forceinline__ void mbar_wait(uint32_t mbar, uint32_t parity) {
    asm volatile(
        "{\n\t.reg .pred P;\n\t"
        "W_%=:\n\t"
        "mbarrier.try_wait.parity.acquire.cta.shared::cta.b64 P, [%0], %1, 0x989680;\n\t"
        "@!P bra W_%=;\n\t}"
        :: "r"(mbar), "r"(parity) : "memory");
}
__device__ __forceinline__ void bulk_cp(uint32_t dst, const void* src, uint32_t bytes,
                                        uint32_t mbar) {
    asm volatile(
        "cp.async.bulk.shared::cluster.global.mbarrier::complete_tx::bytes [%0], [%1], %2, [%3];"
        :: "r"(dst), "l"(src), "r"(bytes), "r"(mbar) : "memory");
}

__global__ void __launch_bounds__(BLK)
fused_k(const float* __restrict__ feat, const int* __restrict__ tgt, int B,
        float* __restrict__ out)
{
    extern __shared__ __align__(16) char dsm[];
    float*        sacc  = (float*)(dsm + SACC_OFF);
    float4*       sacc4 = (float4*)sacc;
    unsigned int* scomb = (unsigned int*)(dsm + SCOMB_OFF);

    __shared__ int      hist[NUM_C];
    __shared__ int      cur[NUM_C];
    __shared__ __align__(8) unsigned long long mbars[NWARP * R];
    __shared__ float    s_red[NWARP], s_sq[NWARP], s_hred[NWARP];
    __shared__ int      s_last;

    const int tid = threadIdx.x;
    const int w = tid >> 5, l = tid & 31;

    const uint32_t smem_base = (uint32_t)__cvta_generic_to_shared(dsm);
    const uint32_t mbar_base = (uint32_t)__cvta_generic_to_shared(mbars);

    const int per = (B + GRID - 1) / GRID;
    const int r0  = blockIdx.x * per;
    int n = B - r0; if (n > per) n = per; if (n < 0) n = 0;

    // zero accumulator + histogram, init mbarriers
    for (int i = tid; i < NUM_C * FD4; i += BLK) sacc4[i] = make_float4(0.f, 0.f, 0.f, 0.f);
    if (tid < NUM_C) hist[tid] = 0;
    if (tid < NWARP * R) mbar_init(mbar_base + tid * 8, 1);
    __syncthreads();

    // ---- phase A: histogram of targets ----
    for (int i = tid; i < n; i += BLK) atomicAdd(&hist[tgt[r0 + i]], 1);
    __syncthreads();

    // ---- exclusive prefix over 64 counts (warp 0) ----
    if (w == 0) {
        int a = hist[l], b = hist[l + 32];
        int ia = a, ib = b;
#pragma unroll
        for (int o = 1; o < 32; o <<= 1) { int t = __shfl_up_sync(0xffffffffu, ia, o); if (l >= o) ia += t; }
#pragma unroll
        for (int o = 1; o < 32; o <<= 1) { int t = __shfl_up_sync(0xffffffffu, ib, o); if (l >= o) ib += t; }
        int totA = __shfl_sync(0xffffffffu, ia, 31);
        cur[l]      = ia - a;
        cur[l + 32] = totA + ib - b;
    }
    __syncthreads();

    // ---- phase B: scatter (rowid | class<<16) into class-sorted order ----
    for (int i = tid; i < n; i += BLK) {
        int t = tgt[r0 + i];                          // L2-hot from phase A
        int pos = atomicAdd(&cur[t], 1);
        scomb[pos] = (unsigned int)i | ((unsigned int)t << 16);
    }
    __syncthreads();

    // ---- phase C: TMA-bulk-staged gather ring, register accumulate ----
    const int p0 = (int)(((long long)n * w) / NWARP);
    const int p1 = (int)(((long long)n * (w + 1)) / NWARP);
    const int total = p1 - p0;
    const int ngrp = (total + G - 1) / G;

    const uint32_t ring0 = smem_base + RING_OFF + w * (R * G * ROWB);
    const uint32_t mb0   = mbar_base + w * R * 8;
    const char* ringc = dsm + RING_OFF + (size_t)w * (R * G * ROWB);

    // prologue: fill ring
    if (l == 0) {
        int pre = ngrp < R ? ngrp : R;
        for (int g = 0; g < pre; g++) {
            int gp0 = p0 + g * G;
            int cnt = p1 - gp0; if (cnt > G) cnt = G;
            mbar_expect_tx(mb0 + g * 8, (uint32_t)(cnt * ROWB));
            for (int u = 0; u < cnt; u++) {
                unsigned int row = scomb[gp0 + u] & 0xffffu;
                bulk_cp(ring0 + g * (G * ROWB) + u * ROWB,
                        feat + (size_t)(r0 + row) * FD, ROWB, mb0 + g * 8);
            }
        }
    }

    float sq0 = 0.f, sq1 = 0.f;
    float4 acc = make_float4(0.f, 0.f, 0.f, 0.f);
    int ccur = (total > 0) ? (int)(scomb[p0] >> 16) : -1;
    int first_run = 1;

    for (int t = 0; t < ngrp; t++) {
        const int slot = t & (R - 1);
        mbar_wait(mb0 + slot * 8, (t >> 2) & 1);
        const int gp0 = p0 + t * G;
        int cnt = p1 - gp0; if (cnt > G) cnt = G;
        const float4* sl = (const float4*)(ringc + slot * (G * ROWB)) + l;

        for (int u = 0; u < cnt; u++) {
            float4 x = sl[u * FD4];                    // LDS.128, conflict-free
            int c = (int)(scomb[gp0 + u] >> 16);
            if (c != ccur) {                           // warp-uniform, rare
                float* s = &sacc[ccur * FD + (l << 2)];
                if (first_run) {
                    atomicAdd(s + 0, acc.x); atomicAdd(s + 1, acc.y);
                    atomicAdd(s + 2, acc.z); atomicAdd(s + 3, acc.w);
                    first_run = 0;
                } else {
                    sacc4[ccur * FD4 + l] = acc;       // exclusive interior run
                }
                acc = make_float4(0.f, 0.f, 0.f, 0.f);
                ccur = c;
            }
            acc.x += x.x; acc.y += x.y; acc.z += x.z; acc.w += x.w;
            if (u & 1) sq1 = fmaf(x.x, x.x, fmaf(x.y, x.y, fmaf(x.z, x.z, fmaf(x.w, x.w, sq1))));
            else       sq0 = fmaf(x.x, x.x, fmaf(x.y, x.y, fmaf(x.z, x.z, fmaf(x.w, x.w, sq0))));
        }

        const int tf = t + R;                          // refill this slot
        if (tf < ngrp && l == 0) {
            int fp0 = p0 + tf * G;
            int fc = p1 - fp0; if (fc > G) fc = G;
            mbar_expect_tx(mb0 + slot * 8, (uint32_t)(fc * ROWB));
            for (int u = 0; u < fc; u++) {
                unsigned int row = scomb[fp0 + u] & 0xffffu;
                bulk_cp(ring0 + slot * (G * ROWB) + u * ROWB,
                        feat + (size_t)(r0 + row) * FD, ROWB, mb0 + slot * 8);
            }
        }
    }
    if (total > 0) {                                   // final run: may span warps -> atomic
        float* s = &sacc[ccur * FD + (l << 2)];
        atomicAdd(s + 0, acc.x); atomicAdd(s + 1, acc.y);
        atomicAdd(s + 2, acc.z); atomicAdd(s + 3, acc.w);
    }
    __syncthreads();

    // ---- block-end merge ----
    for (int i = tid; i < NUM_C * FD; i += BLK)
        atomicAdd(&g_sums[i], sacc[i]);
    if (tid < NUM_C) atomicAdd(&g_counts[tid], hist[tid]);

    float sq = sq0 + sq1;
#pragma unroll
    for (int o = 16; o > 0; o >>= 1) sq += __shfl_down_sync(0xffffffffu, sq, o);
    if (l == 0) s_sq[w] = sq;
    __syncthreads();
    if (tid == 0) {
        float t = 0.f;
#pragma unroll
        for (int k = 0; k < NWARP; k++) t += s_sq[k];
        atomicAdd(&g_sumsq, t);
    }

    __threadfence();
    __syncthreads();
    if (tid == 0) {
        unsigned int tk = atomicAdd(&g_ticket, 1u);
        s_last = (tk == gridDim.x - 1);
    }
    __syncthreads();
    if (!s_last) return;

    // ================= last block: epilogue (cent aliases sacc) =================
    __threadfence();
    float* cent = sacc;

    float ipart = 0.f;
    for (int i = tid; i < NUM_C * FD; i += BLK) {
        const int c = i >> 7;
        float cntc = fmaxf((float)g_counts[c], 1.0f);
        float s  = g_sums[i];
        float ce = s / cntc;
        cent[i]  = ce;
        ipart   += s * ce;
        g_sums[i] = 0.f;                   // reset for next graph replay
    }
    float ssq = 0.f;
    if (tid == 0) { ssq = g_sumsq; g_sumsq = 0.f; g_ticket = 0u; }
    __syncthreads();
    if (tid < NUM_C) g_counts[tid] = 0;

#pragma unroll
    for (int o = 16; o > 0; o >>= 1) ipart += __shfl_down_sync(0xffffffffu, ipart, o);
    if (l == 0) s_red[w] = ipart;
    __syncthreads();

    const float4* c4 = (const float4*)cent;
    float hsum = 0.f;
    for (int i = w; i < NUM_C - 1; i += NWARP) {
        float4 a = c4[i * FD4 + l];
        for (int j = i + 1; j < NUM_C; j++) {
            float4 b = c4[j * FD4 + l];
            float dx = a.x - b.x, dy = a.y - b.y, dz = a.z - b.z, dw = a.w - b.w;
            float d2 = dx * dx + dy * dy + dz * dz + dw * dw;
#pragma unroll
            for (int o = 16; o > 0; o >>= 1) d2 += __shfl_down_sync(0xffffffffu, d2, o);
            if (l == 0) {
                float wt = (i == 1 && j == 2) ? 2.0f : 1.0f;
                hsum += wt * fmaxf(2.0f - d2, 0.0f);     // MARGIN = 2
            }
        }
    }
    if (l == 0) s_hred[w] = hsum;
    __syncthreads();

    if (tid == 0) {
        float isum = 0.f, hs = 0.f;
#pragma unroll
        for (int k = 0; k < NWARP; k++) { isum += s_red[k]; hs += s_hred[k]; }
        out[0] = (ssq - isum) / (float)B + hs / (float)N_PAIRS;
    }
}

extern "C" void kernel_launch(void* const* d_in, const int* in_sizes, int n_in,
                              void* d_out, int out_size) {
    const float* feat = (const float*)d_in[0];
    const int*   tgt  = (const int*)d_in[1];
    const int B = in_sizes[1];
    cudaFuncSetAttribute(fused_k, cudaFuncAttributeMaxDynamicSharedMemorySize, SMEM_DYN);
    fused_k<<<GRID, BLK, SMEM_DYN>>>(feat, tgt, B, (float*)d_out);
}